// round 11
// baseline (speedup 1.0000x reference)
#include <cuda_runtime.h>

// PZCell biquad: one 128-thread block per row, thread = 16-step chunk.
// y[t] = b0 x[t] + b1 x[t-1] + b2 x[t-2] - a1 y[t-1] - a2 y[t-2]   (den == 1)
// All companion-matrix powers carried as Cayley-Hamilton pairs:
//   M^n = k1*M - k2*I   (exact for any a1,a2 since M^2 = -a1*M - a2*I)
// Flow: cp.async per-warp slice -> Phase A zero-state recurrence in swizzled
// SMEM -> warp scan in k-form (A = M^(16*lane) via predicated k-muls) ->
// block carry (M^512 k-pair) -> true entries -> fused-correction store.

namespace {
constexpr int T_LEN   = 2048;
constexpr int B_ROWS  = 4096;
constexpr int THREADS = 128;
}

__device__ __forceinline__ int swz(int c, int g) {
    return c * 16 + ((g ^ ((c >> 1) & 3)) << 2);
}

__device__ __forceinline__ void cp_async16(float* dst, const float* src) {
    unsigned s = (unsigned)__cvta_generic_to_shared(dst);
    asm volatile("cp.async.cg.shared.global [%0], [%1], 16;" :: "r"(s), "l"(src));
}
__device__ __forceinline__ void cp_commit() { asm volatile("cp.async.commit_group;"); }
__device__ __forceinline__ void cp_wait0()  { asm volatile("cp.async.wait_group 0;" ::: "memory"); }

struct Coef { float a1, a2, A2, Bc, b0, b1, b2; };
struct K2   { float k1, k2; };   // represents k1*M - k2*I

__device__ __forceinline__ K2 ksq(K2 a, float a1, float a2) {
    float t = a.k1 * a.k1;
    K2 r;
    r.k1 = -fmaf(a1, t, 2.f * a.k1 * a.k2);
    r.k2 =  fmaf(a2, t, -a.k2 * a.k2);
    return r;
}
__device__ __forceinline__ K2 kmul(K2 p, K2 q, float a1, float a2) {
    float t = p.k1 * q.k1;
    K2 r;
    r.k1 = -fmaf(a1, t, fmaf(p.k1, q.k2, p.k2 * q.k1));
    r.k2 =  fmaf(a2, t, -p.k2 * q.k2);
    return r;
}

// 4 recurrence steps; updates (x1,x2,p,q), returns z quad
__device__ __forceinline__ float4 step4(const Coef& c, float4 xv,
                                        float& x1, float& x2, float& p, float& q)
{
    float u0 = fmaf(c.b0, xv.x, fmaf(c.b1, x1,   c.b2 * x2));
    float u1 = fmaf(c.b0, xv.y, fmaf(c.b1, xv.x, c.b2 * x1));
    float u2 = fmaf(c.b0, xv.z, fmaf(c.b1, xv.y, c.b2 * xv.x));
    float u3 = fmaf(c.b0, xv.w, fmaf(c.b1, xv.z, c.b2 * xv.y));
    x2 = xv.z; x1 = xv.w;
    float w1 = fmaf(-c.a1, u0, u1);
    float w3 = fmaf(-c.a1, u2, u3);
    float yA = fmaf(-c.a1, p,  fmaf(-c.a2, q,  u0));
    float yB = fmaf( c.A2, p,  fmaf( c.Bc, q,  w1));
    float yC = fmaf(-c.a1, yB, fmaf(-c.a2, yA, u2));
    float yD = fmaf( c.A2, yB, fmaf( c.Bc, yA, w3));
    p = yD; q = yC;
    return make_float4(yA, yB, yC, yD);
}

__global__ void __launch_bounds__(THREADS, 10)
pzB_kernel(const float* __restrict__ x, const float* __restrict__ gain_ri,
           const float* __restrict__ poles_ri, const float* __restrict__ zeros_ri,
           float* __restrict__ out)
{
    __shared__ float  tile[2048];   // row data (in-place x -> z)
    __shared__ float2 ent[128];     // per-chunk true entry (Ex,Ey)
    __shared__ float  wex[8];       // per-warp zero-entry exit (dx,dy) x 4

    const int tid  = threadIdx.x;
    const int lane = tid & 31;
    const int w    = tid >> 5;
    const int row  = blockIdx.x;
    const float* xr = x   + (long)row * T_LEN;
    float*       yr = out + (long)row * T_LEN;

    // warp-edge boundary via gmem (independent of SMEM residency)
    float gx1 = 0.f, gx2 = 0.f;
    if (lane == 0 && w > 0) { gx1 = xr[w * 512 - 1]; gx2 = xr[w * 512 - 2]; }

    // ---- cp.async: warp w loads its own 2KB slice, coalesced ----
    #pragma unroll
    for (int i = 0; i < 4; ++i) {
        int ch = w * 32 + i * 8 + (lane >> 2);
        cp_async16(tile + swz(ch, lane & 3), xr + w * 512 + i * 128 + lane * 4);
    }
    cp_commit();

    // ---- coefficients + k-pair powers (overlap with loads) ----
    Coef c;
    {
        const float gr = gain_ri[0],  gi = gain_ri[1];
        const float pr0 = poles_ri[0], pi0 = poles_ri[1];
        const float pr1 = poles_ri[2], pi1 = poles_ri[3];
        const float zr0 = zeros_ri[0], zi0 = zeros_ri[1];
        const float zr1 = zeros_ri[2], zi1 = zeros_ri[3];
        c.a1 = -(pr0 + pr1);
        c.a2 = pr0 * pr1 - pi0 * pi1;
        const float zc1r = -(zr0 + zr1), zc1i = -(zi0 + zi1);
        const float zc2r = zr0 * zr1 - zi0 * zi1;
        const float zc2i = zr0 * zi1 + zi0 * zr1;
        c.b0 = gr;
        c.b1 = gr * zc1r - gi * zc1i;
        c.b2 = gr * zc2r - gi * zc2i;
        c.A2 = c.a1 * c.a1 - c.a2;
        c.Bc = c.a1 * c.a2;
    }
    const float a1 = c.a1, a2 = c.a2;
    K2 M1k  = { 1.f, 0.f };
    K2 M2k  = ksq(M1k, a1, a2);
    K2 M4k  = ksq(M2k, a1, a2);
    K2 M8k  = ksq(M4k, a1, a2);
    K2 M16k = ksq(M8k, a1, a2);
    K2 M12k = kmul(M8k, M4k, a1, a2);

    cp_wait0();
    __syncwarp();    // this warp's slice resident & visible

    // ---- boundary x[-1], x[-2] of this thread's chunk ----
    float x1, x2;
    if (lane > 0) {
        int cc = tid - 1;   // same warp slice
        int off = cc * 16 + ((3 ^ ((cc >> 1) & 3)) << 2);
        x1 = tile[off + 3];
        x2 = tile[off + 2];
    } else {
        x1 = gx1; x2 = gx2;   // tid==0 -> zeros
    }
    __syncwarp();    // boundary reads done before Phase A overwrites tails

    // ---- Phase A: 16-step zero-entry recurrence in place ----
    float p = 0.f, q = 0.f;
    #pragma unroll
    for (int g = 0; g < 4; ++g) {
        float4 xv = *reinterpret_cast<float4*>(tile + swz(tid, g));
        float4 zv = step4(c, xv, x1, x2, p, q);
        *reinterpret_cast<float4*>(tile + swz(tid, g)) = zv;
    }

    // ---- warp scan (T = M^16 in k-form), A = M^(16*lane) via k-muls ----
    K2 m = M16k;
    K2 A = { 0.f, -1.f };            // identity
    float vx = p, vy = q;
    #pragma unroll
    for (int i = 0; i < 5; ++i) {
        float ox = __shfl_up_sync(0xffffffffu, vx, 1u << i);
        float oy = __shfl_up_sync(0xffffffffu, vy, 1u << i);
        if (lane >= (1 << i)) {
            float t = fmaf(-a1, ox, -a2 * oy);
            vx = fmaf(m.k1, t,  fmaf(-m.k2, ox, vx));
            vy = fmaf(m.k1, ox, fmaf(-m.k2, oy, vy));
        }
        if ((lane >> i) & 1) A = kmul(m, A, a1, a2);
        if (i < 4) m = ksq(m, a1, a2);
    }
    // m = M^256 in k-form
    K2 M512k = ksq(m, a1, a2);

    float ex = __shfl_up_sync(0xffffffffu, vx, 1);   // zero-seeded exclusive entry
    float ey = __shfl_up_sync(0xffffffffu, vy, 1);
    if (lane == 0) { ex = 0.f; ey = 0.f; }
    if (lane == 31) { wex[2 * w] = vx; wex[2 * w + 1] = vy; }   // warp exit d_w

    __syncthreads();

    // ---- cross-warp affine carry: C_w = f_{w-1}(...f_0(0)) ----
    float Cx = 0.f, Cy = 0.f;
    if (w > 0) { Cx = wex[0]; Cy = wex[1]; }
    if (w > 1) {
        float t  = fmaf(-a1, Cx, -a2 * Cy);
        float nx = fmaf(M512k.k1, t,  fmaf(-M512k.k2, Cx, wex[2]));
        float ny = fmaf(M512k.k1, Cx, fmaf(-M512k.k2, Cy, wex[3]));
        Cx = nx; Cy = ny;
    }
    if (w > 2) {
        float t  = fmaf(-a1, Cx, -a2 * Cy);
        float nx = fmaf(M512k.k1, t,  fmaf(-M512k.k2, Cx, wex[4]));
        float ny = fmaf(M512k.k1, Cx, fmaf(-M512k.k2, Cy, wex[5]));
        Cx = nx; Cy = ny;
    }
    // true entry of this thread's chunk: E = A*C + e
    {
        float t  = fmaf(-a1, Cx, -a2 * Cy);
        float Ex = fmaf(A.k1, t,  fmaf(-A.k2, Cx, ex));
        float Ey = fmaf(A.k1, Cx, fmaf(-A.k2, Cy, ey));
        ent[tid] = make_float2(Ex, Ey);
    }

    __syncthreads();

    // ---- coalesced store with fused homogeneous correction ----
    // pos = it*512 + tid*4: chunk ch = it*32 + (tid>>2), W = M^(4*(tid&3)).
    const int j = tid & 3;
    const float W1 = (j == 0) ? 0.f  : (j == 1) ? M4k.k1 : (j == 2) ? M8k.k1 : M12k.k1;
    const float W2 = (j == 0) ? -1.f : (j == 1) ? M4k.k2 : (j == 2) ? M8k.k2 : M12k.k2;
    #pragma unroll
    for (int it = 0; it < 4; ++it) {
        int ch = it * 32 + (tid >> 2);
        float2 E = ent[ch];
        float t  = fmaf(-a1, E.x, -a2 * E.y);
        float s1 = fmaf(W1, t,   fmaf(-W2, E.x, 0.f));
        float s2 = fmaf(W1, E.x, fmaf(-W2, E.y, 0.f));
        float hA = fmaf(-a1, s1, -a2 * s2);
        float hB = fmaf( c.A2, s1,  c.Bc * s2);
        float hC = fmaf(-a1, hB, -a2 * hA);
        float hD = fmaf( c.A2, hB,  c.Bc * hA);
        float4 zv = *reinterpret_cast<float4*>(tile + swz(ch, j));
        zv.x += hA; zv.y += hB; zv.z += hC; zv.w += hD;
        *reinterpret_cast<float4*>(yr + it * 512 + tid * 4) = zv;
    }
}

extern "C" void kernel_launch(void* const* d_in, const int* in_sizes, int n_in,
                              void* d_out, int out_size) {
    (void)in_sizes; (void)n_in; (void)out_size;
    const float* x        = (const float*)d_in[0];
    const float* gain_ri  = (const float*)d_in[1];
    const float* poles_ri = (const float*)d_in[2];
    const float* zeros_ri = (const float*)d_in[3];
    float* out = (float*)d_out;

    pzB_kernel<<<B_ROWS, THREADS>>>(x, gain_ri, poles_ri, zeros_ri, out);
}

// round 12
// speedup vs baseline: 1.1569x; 1.1569x over previous
#include <cuda_runtime.h>

// PZCell biquad, warp-per-row parallel scan, 3-buffer cp.async ring (R7
// skeleton) with Cayley-Hamilton k-pair matrix powers: M^n = k1*M - k2*I
// (exact: M^2 = -a1*M - a2*I).
// y[t] = b0 x[t] + b1 x[t-1] + b2 x[t-2] - a1 y[t-1] - a2 y[t-2]   (den == 1)

namespace {
constexpr int T_LEN   = 2048;
constexpr int B_ROWS  = 4096;
constexpr int QSTEPS  = 512;                // steps per quarter
constexpr int QTILE   = 512;                // floats per quarter buffer (2KB)
constexpr int NBUF    = 3;                  // ring buffers
constexpr int RPB     = 2;                  // rows (warps) per block
constexpr int THREADS = 32 * RPB;
constexpr int WARP_SMEM  = NBUF * QTILE;    // 1536 floats
constexpr int SMEM_BYTES = RPB * WARP_SMEM * (int)sizeof(float);  // 12288
}

// chunk c (0..31, 16 floats), granule g (0..3): conflict-free for all passes
__device__ __forceinline__ int swz(int c, int g) {
    return c * 16 + ((g ^ ((c >> 1) & 3)) << 2);
}

__device__ __forceinline__ void cp_async16(float* dst, const float* src) {
    unsigned s = (unsigned)__cvta_generic_to_shared(dst);
    asm volatile("cp.async.cg.shared.global [%0], [%1], 16;" :: "r"(s), "l"(src));
}
__device__ __forceinline__ void cp_commit() { asm volatile("cp.async.commit_group;"); }
template <int N>
__device__ __forceinline__ void cp_wait() {
    asm volatile("cp.async.wait_group %0;" :: "n"(N) : "memory");
}

struct Coef { float a1, a2, A2, Bc, b0, b1, b2; };
struct K2   { float k1, k2; };   // k1*M - k2*I

__device__ __forceinline__ K2 ksq(K2 a, float a1, float a2) {
    float t = a.k1 * a.k1;
    K2 r;
    r.k1 = -fmaf(a1, t, 2.f * a.k1 * a.k2);
    r.k2 =  fmaf(a2, t, -a.k2 * a.k2);
    return r;
}
__device__ __forceinline__ K2 kmul(K2 p, K2 q, float a1, float a2) {
    float t = p.k1 * q.k1;
    K2 r;
    r.k1 = -fmaf(a1, t, fmaf(p.k1, q.k2, p.k2 * q.k1));
    r.k2 =  fmaf(a2, t, -p.k2 * q.k2);
    return r;
}
// apply (k1*M - k2*I) to (sx,sy); M = [[-a1,-a2],[1,0]]
__device__ __forceinline__ void kapply(K2 k, float a1, float a2,
                                       float sx, float sy, float& rx, float& ry) {
    float t = fmaf(-a1, sx, -a2 * sy);
    rx = fmaf(k.k1, t,  -k.k2 * sx);
    ry = fmaf(k.k1, sx, -k.k2 * sy);
}

// issue one quarter's coalesced cp.async load into buf
__device__ __forceinline__ void issue_quarter_load(
    float* buf, const float* __restrict__ xq, int lane)
{
    #pragma unroll
    for (int k = 0; k < 4; ++k) {
        int ch = k * 8 + (lane >> 2);
        cp_async16(buf + swz(ch, lane & 3), xq + k * 128 + lane * 4);
    }
    cp_commit();
}

// one 512-step quarter. Px,Py = row exit state (updated); bx1,bx2 = x tail.
__device__ __forceinline__ void quarter_pass(
    float* buf, float* __restrict__ yq, int lane, const Coef& c,
    float W1, float W2, K2 M16k,
    float& Px, float& Py, float& bx1, float& bx2)
{
    const float a1 = c.a1, a2 = c.a2;

    // ---- boundary x[-1], x[-2] ----
    float x1, x2;
    if (lane > 0) {
        int cc = lane - 1;
        int off = cc * 16 + ((3 ^ ((cc >> 1) & 3)) << 2);   // granule 3 = f 12..15
        x1 = buf[off + 3];   // f=15
        x2 = buf[off + 2];   // f=14
    } else {
        x1 = bx1; x2 = bx2;
    }
    __syncwarp();

    // ---- Phase A: zero-entry-state recurrence in place ----
    float p = 0.f, q = 0.f;
    #pragma unroll
    for (int g = 0; g < 4; ++g) {
        float4 xv = *reinterpret_cast<float4*>(buf + swz(lane, g));
        float u0 = fmaf(c.b0, xv.x, fmaf(c.b1, x1,   c.b2 * x2));
        float u1 = fmaf(c.b0, xv.y, fmaf(c.b1, xv.x, c.b2 * x1));
        float u2 = fmaf(c.b0, xv.z, fmaf(c.b1, xv.y, c.b2 * xv.x));
        float u3 = fmaf(c.b0, xv.w, fmaf(c.b1, xv.z, c.b2 * xv.y));
        x2 = xv.z; x1 = xv.w;
        float w1 = fmaf(-a1, u0, u1);
        float w3 = fmaf(-a1, u2, u3);
        float yA = fmaf(-a1, p,  fmaf(-a2, q,  u0));
        float yB = fmaf( c.A2, p,  fmaf( c.Bc, q,  w1));
        float yC = fmaf(-a1, yB, fmaf(-a2, yA, u2));
        float yD = fmaf( c.A2, yB, fmaf( c.Bc, yA, w3));
        p = yD; q = yC;
        *reinterpret_cast<float4*>(buf + swz(lane, g)) = make_float4(yA, yB, yC, yD);
    }
    // x tail of this quarter (lane 31 holds x[511], x[510])
    float nbx1 = __shfl_sync(0xffffffffu, x1, 31);
    float nbx2 = __shfl_sync(0xffffffffu, x2, 31);
    bx1 = nbx1; bx2 = nbx2;

    // ---- seeded affine Kogge-Stone scan (T = M^16, k-form) ----
    K2 m = M16k;
    float vx = p, vy = q;
    if (lane == 0) {   // fold row carry into seed: d0' = d0 + T*P
        float tx, ty;
        kapply(m, a1, a2, Px, Py, tx, ty);
        vx += tx; vy += ty;
    }
    #pragma unroll
    for (int i = 0; i < 5; ++i) {
        float ox = __shfl_up_sync(0xffffffffu, vx, 1u << i);
        float oy = __shfl_up_sync(0xffffffffu, vy, 1u << i);
        if (lane >= (1 << i)) {
            float t = fmaf(-a1, ox, -a2 * oy);
            vx = fmaf(m.k1, t,  fmaf(-m.k2, ox, vx));
            vy = fmaf(m.k1, ox, fmaf(-m.k2, oy, vy));
        }
        if (i < 4) m = ksq(m, a1, a2);
    }
    // exclusive entry per 16-step chunk; lane 0 entry = carried P
    float ex = __shfl_up_sync(0xffffffffu, vx, 1);
    float ey = __shfl_up_sync(0xffffffffu, vy, 1);
    if (lane == 0) { ex = Px; ey = Py; }
    // row exit state = inclusive at lane 31 (carry included via seed)
    Px = __shfl_sync(0xffffffffu, vx, 31);
    Py = __shfl_sync(0xffffffffu, vy, 31);

    __syncwarp();

    // ---- store pass with fused homogeneous correction ----
    // t = k*128 + lane*4: chunk ch = 8k + (lane>>2), f0 = (lane&3)*4,
    // seed = W * entry with W = M^f0 as k-pair (W1,W2).
    #pragma unroll
    for (int k = 0; k < 4; ++k) {
        int ch = k * 8 + (lane >> 2);
        float exc = __shfl_sync(0xffffffffu, ex, ch);
        float eyc = __shfl_sync(0xffffffffu, ey, ch);
        float t  = fmaf(-a1, exc, -a2 * eyc);
        float s1 = fmaf(W1, t,   -W2 * exc);
        float s2 = fmaf(W1, exc, -W2 * eyc);
        float hA = fmaf(-a1, s1, -a2 * s2);
        float hB = fmaf( c.A2, s1,  c.Bc * s2);
        float hC = fmaf(-a1, hB, -a2 * hA);
        float hD = fmaf( c.A2, hB,  c.Bc * hA);
        float4 zv = *reinterpret_cast<float4*>(buf + swz(ch, lane & 3));
        zv.x += hA; zv.y += hB; zv.z += hC; zv.w += hD;
        *reinterpret_cast<float4*>(yq + k * 128 + lane * 4) = zv;
    }
    __syncwarp();
}

__global__ void __launch_bounds__(THREADS, 16)
pzC_kernel(const float* __restrict__ x, const float* __restrict__ gain_ri,
           const float* __restrict__ poles_ri, const float* __restrict__ zeros_ri,
           float* __restrict__ out)
{
    extern __shared__ float sbuf[];
    const int lane = threadIdx.x & 31;
    const int w    = threadIdx.x >> 5;
    const int row  = blockIdx.x * RPB + w;
    const float* xr = x   + (long)row * T_LEN;
    float*       yr = out + (long)row * T_LEN;
    float* sb = sbuf + w * WARP_SMEM;

    // ---- issue loads for quarters 0..2 (3 commit groups) ----
    issue_quarter_load(sb + 0 * QTILE, xr + 0 * QSTEPS, lane);
    issue_quarter_load(sb + 1 * QTILE, xr + 1 * QSTEPS, lane);
    issue_quarter_load(sb + 2 * QTILE, xr + 2 * QSTEPS, lane);

    // ---- coefficients + k-pair powers (overlap with cp.async) ----
    Coef c;
    {
        const float gr = gain_ri[0],  gi = gain_ri[1];
        const float pr0 = poles_ri[0], pi0 = poles_ri[1];
        const float pr1 = poles_ri[2], pi1 = poles_ri[3];
        const float zr0 = zeros_ri[0], zi0 = zeros_ri[1];
        const float zr1 = zeros_ri[2], zi1 = zeros_ri[3];
        c.a1 = -(pr0 + pr1);
        c.a2 = pr0 * pr1 - pi0 * pi1;
        const float zc1r = -(zr0 + zr1), zc1i = -(zi0 + zi1);
        const float zc2r = zr0 * zr1 - zi0 * zi1;
        const float zc2i = zr0 * zi1 + zi0 * zr1;
        c.b0 = gr;
        c.b1 = gr * zc1r - gi * zc1i;
        c.b2 = gr * zc2r - gi * zc2i;
        c.A2 = c.a1 * c.a1 - c.a2;
        c.Bc = c.a1 * c.a2;
    }
    const float a1 = c.a1, a2 = c.a2;
    K2 M1k  = { 1.f, 0.f };
    K2 M4k  = ksq(ksq(M1k, a1, a2), a1, a2);
    K2 M8k  = ksq(M4k, a1, a2);
    K2 M16k = ksq(M8k, a1, a2);
    K2 M12k = kmul(M8k, M4k, a1, a2);
    // W = M^(4*(lane&3)) as k-pair
    const int j = lane & 3;
    const float W1 = (j == 0) ? 0.f  : (j == 1) ? M4k.k1 : (j == 2) ? M8k.k1 : M12k.k1;
    const float W2 = (j == 0) ? -1.f : (j == 1) ? M4k.k2 : (j == 2) ? M8k.k2 : M12k.k2;

    float Px = 0.f, Py = 0.f;     // row exit state carry
    float bx1 = 0.f, bx2 = 0.f;   // x tail carry

    cp_wait<2>(); __syncwarp();   // q0 resident
    quarter_pass(sb + 0 * QTILE, yr + 0 * QSTEPS, lane, c, W1, W2, M16k, Px, Py, bx1, bx2);

    // buf0 drained -> issue q3 into it (hidden under q1+q2 compute)
    issue_quarter_load(sb + 0 * QTILE, xr + 3 * QSTEPS, lane);

    cp_wait<2>(); __syncwarp();   // q1 resident (q2, q3 may be outstanding)
    quarter_pass(sb + 1 * QTILE, yr + 1 * QSTEPS, lane, c, W1, W2, M16k, Px, Py, bx1, bx2);
    cp_wait<1>(); __syncwarp();   // q2 resident
    quarter_pass(sb + 2 * QTILE, yr + 2 * QSTEPS, lane, c, W1, W2, M16k, Px, Py, bx1, bx2);
    cp_wait<0>(); __syncwarp();   // q3 resident
    quarter_pass(sb + 0 * QTILE, yr + 3 * QSTEPS, lane, c, W1, W2, M16k, Px, Py, bx1, bx2);
}

extern "C" void kernel_launch(void* const* d_in, const int* in_sizes, int n_in,
                              void* d_out, int out_size) {
    (void)in_sizes; (void)n_in; (void)out_size;
    const float* x        = (const float*)d_in[0];
    const float* gain_ri  = (const float*)d_in[1];
    const float* poles_ri = (const float*)d_in[2];
    const float* zeros_ri = (const float*)d_in[3];
    float* out = (float*)d_out;

    cudaFuncSetAttribute(pzC_kernel, cudaFuncAttributeMaxDynamicSharedMemorySize, SMEM_BYTES);
    pzC_kernel<<<B_ROWS / RPB, THREADS, SMEM_BYTES>>>(x, gain_ri, poles_ri, zeros_ri, out);
}

// round 13
// speedup vs baseline: 1.1597x; 1.0025x over previous
#include <cuda_runtime.h>

// PZCell biquad: one 64-thread block per row; 2 warps x (32 lanes x 32 steps).
// y[t] = b0 x[t] + b1 x[t-1] + b2 x[t-2] - a1 y[t-1] - a2 y[t-2]   (den == 1)
// Matrix powers as Cayley-Hamilton k-pairs: M^n = k1*M - k2*I.
// Flow: per-warp cp.async half-slice -> Phase A zero-state recurrence in
// swizzled SMEM -> warp scan (T=M^32, A=M^(32*lane) in-loop) -> 2-warp
// combine via SMEM (carry = warp0 exit) -> entries -> fused-correction store.

namespace {
constexpr int T_LEN   = 2048;
constexpr int B_ROWS  = 4096;
constexpr int THREADS = 64;
}

// chunk c (0..63, 32 floats), granule g (0..7): XOR swizzle, conflict-free
// per 8-lane group for all access patterns used here.
__device__ __forceinline__ int swz(int c, int g) {
    return c * 32 + ((g ^ (c & 7)) << 2);
}

__device__ __forceinline__ void cp_async16(float* dst, const float* src) {
    unsigned s = (unsigned)__cvta_generic_to_shared(dst);
    asm volatile("cp.async.cg.shared.global [%0], [%1], 16;" :: "r"(s), "l"(src));
}
__device__ __forceinline__ void cp_commit() { asm volatile("cp.async.commit_group;"); }
__device__ __forceinline__ void cp_wait0()  { asm volatile("cp.async.wait_group 0;" ::: "memory"); }

struct Coef { float a1, a2, A2, Bc, b0, b1, b2; };
struct K2   { float k1, k2; };   // k1*M - k2*I

__device__ __forceinline__ K2 ksq(K2 a, float a1, float a2) {
    float t = a.k1 * a.k1;
    K2 r;
    r.k1 = -fmaf(a1, t, 2.f * a.k1 * a.k2);
    r.k2 =  fmaf(a2, t, -a.k2 * a.k2);
    return r;
}
__device__ __forceinline__ K2 kmul(K2 p, K2 q, float a1, float a2) {
    float t = p.k1 * q.k1;
    K2 r;
    r.k1 = -fmaf(a1, t, fmaf(p.k1, q.k2, p.k2 * q.k1));
    r.k2 =  fmaf(a2, t, -p.k2 * q.k2);
    return r;
}

__global__ void __launch_bounds__(THREADS, 16)
pzD_kernel(const float* __restrict__ x, const float* __restrict__ gain_ri,
           const float* __restrict__ poles_ri, const float* __restrict__ zeros_ri,
           float* __restrict__ out)
{
    __shared__ float  tile[2048];   // whole row, in-place x -> z
    __shared__ float2 ent[64];      // per-chunk true entry
    __shared__ float2 wex;          // warp-0 inclusive exit

    const int tid  = threadIdx.x;
    const int lane = tid & 31;
    const int w    = tid >> 5;
    const int row  = blockIdx.x;
    const float* xr = x   + (long)row * T_LEN;
    float*       yr = out + (long)row * T_LEN;

    // warp-edge boundary (x[1023], x[1022]) for warp 1 lane 0, via gmem
    float gx1 = 0.f, gx2 = 0.f;
    if (lane == 0 && w == 1) { gx1 = xr[1023]; gx2 = xr[1022]; }

    // ---- cp.async: warp w loads its own 4KB half, coalesced ----
    #pragma unroll
    for (int k = 0; k < 8; ++k) {
        int ch = w * 32 + k * 4 + (lane >> 3);
        cp_async16(tile + swz(ch, lane & 7), xr + w * 1024 + k * 128 + lane * 4);
    }
    cp_commit();

    // ---- coefficients + k-pair powers (overlap with loads) ----
    Coef c;
    {
        const float gr = gain_ri[0],  gi = gain_ri[1];
        const float pr0 = poles_ri[0], pi0 = poles_ri[1];
        const float pr1 = poles_ri[2], pi1 = poles_ri[3];
        const float zr0 = zeros_ri[0], zi0 = zeros_ri[1];
        const float zr1 = zeros_ri[2], zi1 = zeros_ri[3];
        c.a1 = -(pr0 + pr1);
        c.a2 = pr0 * pr1 - pi0 * pi1;
        const float zc1r = -(zr0 + zr1), zc1i = -(zi0 + zi1);
        const float zc2r = zr0 * zr1 - zi0 * zi1;
        const float zc2i = zr0 * zi1 + zi0 * zr1;
        c.b0 = gr;
        c.b1 = gr * zc1r - gi * zc1i;
        c.b2 = gr * zc2r - gi * zc2i;
        c.A2 = c.a1 * c.a1 - c.a2;
        c.Bc = c.a1 * c.a2;
    }
    const float a1 = c.a1, a2 = c.a2;
    K2 M1k  = { 1.f, 0.f };
    K2 M4k  = ksq(ksq(M1k, a1, a2), a1, a2);
    K2 M8k  = ksq(M4k, a1, a2);
    K2 M16k = ksq(M8k, a1, a2);
    K2 M32k = ksq(M16k, a1, a2);

    cp_wait0();
    __syncwarp();   // own warp's half resident & visible warp-wide

    // ---- boundary x[-1], x[-2] of this thread's 32-step chunk ----
    float x1, x2;
    if (lane > 0) {
        int cc = tid - 1;                       // same warp half
        int off = cc * 32 + ((7 ^ (cc & 7)) << 2);   // granule 7 = steps 28..31
        x1 = tile[off + 3];
        x2 = tile[off + 2];
    } else {
        x1 = gx1; x2 = gx2;                     // tid==0 -> zeros
    }
    __syncwarp();   // boundary reads done before Phase A overwrites tails

    // ---- Phase A: 32-step zero-entry recurrence in place ----
    float p = 0.f, q = 0.f;
    #pragma unroll
    for (int g = 0; g < 8; ++g) {
        float4 xv = *reinterpret_cast<float4*>(tile + swz(tid, g));
        float u0 = fmaf(c.b0, xv.x, fmaf(c.b1, x1,   c.b2 * x2));
        float u1 = fmaf(c.b0, xv.y, fmaf(c.b1, xv.x, c.b2 * x1));
        float u2 = fmaf(c.b0, xv.z, fmaf(c.b1, xv.y, c.b2 * xv.x));
        float u3 = fmaf(c.b0, xv.w, fmaf(c.b1, xv.z, c.b2 * xv.y));
        x2 = xv.z; x1 = xv.w;
        float w1 = fmaf(-a1, u0, u1);
        float w3 = fmaf(-a1, u2, u3);
        float yA = fmaf(-a1, p,  fmaf(-a2, q,  u0));
        float yB = fmaf( c.A2, p,  fmaf( c.Bc, q,  w1));
        float yC = fmaf(-a1, yB, fmaf(-a2, yA, u2));
        float yD = fmaf( c.A2, yB, fmaf( c.Bc, yA, w3));
        p = yD; q = yC;
        *reinterpret_cast<float4*>(tile + swz(tid, g)) = make_float4(yA, yB, yC, yD);
    }

    // ---- warp scan (T = M^32 k-form), A = M^(32*lane) built in-loop ----
    K2 m = M32k;
    K2 A = { 0.f, -1.f };   // identity
    float vx = p, vy = q;
    #pragma unroll
    for (int i = 0; i < 5; ++i) {
        float ox = __shfl_up_sync(0xffffffffu, vx, 1u << i);
        float oy = __shfl_up_sync(0xffffffffu, vy, 1u << i);
        if (lane >= (1 << i)) {
            float t = fmaf(-a1, ox, -a2 * oy);
            vx = fmaf(m.k1, t,  fmaf(-m.k2, ox, vx));
            vy = fmaf(m.k1, ox, fmaf(-m.k2, oy, vy));
        }
        if ((lane >> i) & 1) A = kmul(m, A, a1, a2);
        if (i < 4) m = ksq(m, a1, a2);
    }
    float ex = __shfl_up_sync(0xffffffffu, vx, 1);   // warp-local exclusive entry
    float ey = __shfl_up_sync(0xffffffffu, vy, 1);
    if (lane == 0) { ex = 0.f; ey = 0.f; }
    if (w == 0 && lane == 31) wex = make_float2(vx, vy);   // warp-0 exit

    __syncthreads();

    // ---- true entries: warp 0: E = e; warp 1: E = A*C + e, C = warp0 exit ----
    float Ex = ex, Ey = ey;
    if (w == 1) {
        float Cx = wex.x, Cy = wex.y;
        float t = fmaf(-a1, Cx, -a2 * Cy);
        Ex = fmaf(A.k1, t,  fmaf(-A.k2, Cx, ex));
        Ey = fmaf(A.k1, Cx, fmaf(-A.k2, Cy, ey));
    }
    ent[tid] = make_float2(Ex, Ey);

    __syncthreads();

    // ---- coalesced store with fused homogeneous correction ----
    // pos = it*256 + tid*4: chunk ch = it*8 + (tid>>3), granule j = tid&7,
    // seed = W*E(ch), W = M^(4j) as k-pair (per-lane constant).
    const int j = tid & 7;
    K2 W = { 0.f, -1.f };
    if (j & 1) W = M4k;
    if (j & 2) W = kmul(M8k,  W, a1, a2);
    if (j & 4) W = kmul(M16k, W, a1, a2);
    #pragma unroll
    for (int it = 0; it < 8; ++it) {
        int ch = it * 8 + (tid >> 3);
        float2 E = ent[ch];
        float t  = fmaf(-a1, E.x, -a2 * E.y);
        float s1 = fmaf(W.k1, t,   -W.k2 * E.x);
        float s2 = fmaf(W.k1, E.x, -W.k2 * E.y);
        float hA = fmaf(-a1, s1, -a2 * s2);
        float hB = fmaf( c.A2, s1,  c.Bc * s2);
        float hC = fmaf(-a1, hB, -a2 * hA);
        float hD = fmaf( c.A2, hB,  c.Bc * hA);
        float4 zv = *reinterpret_cast<float4*>(tile + swz(ch, j));
        zv.x += hA; zv.y += hB; zv.z += hC; zv.w += hD;
        *reinterpret_cast<float4*>(yr + it * 256 + tid * 4) = zv;
    }
}

extern "C" void kernel_launch(void* const* d_in, const int* in_sizes, int n_in,
                              void* d_out, int out_size) {
    (void)in_sizes; (void)n_in; (void)out_size;
    const float* x        = (const float*)d_in[0];
    const float* gain_ri  = (const float*)d_in[1];
    const float* poles_ri = (const float*)d_in[2];
    const float* zeros_ri = (const float*)d_in[3];
    float* out = (float*)d_out;

    pzD_kernel<<<B_ROWS, THREADS>>>(x, gain_ri, poles_ri, zeros_ri, out);
}

// round 14
// speedup vs baseline: 1.1626x; 1.0025x over previous
#include <cuda_runtime.h>

// PZCell biquad: one 64-thread block per row; 2 warps x (32 lanes x 32 steps).
// y[t] = b0 x[t] + b1 x[t-1] + b2 x[t-2] - a1 y[t-1] - a2 y[t-2]   (den == 1)
// Matrix powers as Cayley-Hamilton k-pairs: M^n = k1*M - k2*I.
// Flow: per-warp cp.async half-slice -> Phase A zero-state recurrence in
// swizzled SMEM -> warp scan (T=M^32, A=M^(32*lane) in-loop) -> 2-warp
// combine via SMEM (carry = warp0 exit) -> entries -> fused-correction store.
// R14: residency target raised to 24 blocks/SM (was 16) — regs 40 and
// ~8.7KB SMEM/block admit it; grid 4096/148 = 27.7 -> 1.15 waves.

namespace {
constexpr int T_LEN   = 2048;
constexpr int B_ROWS  = 4096;
constexpr int THREADS = 64;
}

// chunk c (0..63, 32 floats), granule g (0..7): XOR swizzle, conflict-free
// per 8-lane group for all access patterns used here.
__device__ __forceinline__ int swz(int c, int g) {
    return c * 32 + ((g ^ (c & 7)) << 2);
}

__device__ __forceinline__ void cp_async16(float* dst, const float* src) {
    unsigned s = (unsigned)__cvta_generic_to_shared(dst);
    asm volatile("cp.async.cg.shared.global [%0], [%1], 16;" :: "r"(s), "l"(src));
}
__device__ __forceinline__ void cp_commit() { asm volatile("cp.async.commit_group;"); }
__device__ __forceinline__ void cp_wait0()  { asm volatile("cp.async.wait_group 0;" ::: "memory"); }

struct Coef { float a1, a2, A2, Bc, b0, b1, b2; };
struct K2   { float k1, k2; };   // k1*M - k2*I

__device__ __forceinline__ K2 ksq(K2 a, float a1, float a2) {
    float t = a.k1 * a.k1;
    K2 r;
    r.k1 = -fmaf(a1, t, 2.f * a.k1 * a.k2);
    r.k2 =  fmaf(a2, t, -a.k2 * a.k2);
    return r;
}
__device__ __forceinline__ K2 kmul(K2 p, K2 q, float a1, float a2) {
    float t = p.k1 * q.k1;
    K2 r;
    r.k1 = -fmaf(a1, t, fmaf(p.k1, q.k2, p.k2 * q.k1));
    r.k2 =  fmaf(a2, t, -p.k2 * q.k2);
    return r;
}

__global__ void __launch_bounds__(THREADS, 24)
pzE_kernel(const float* __restrict__ x, const float* __restrict__ gain_ri,
           const float* __restrict__ poles_ri, const float* __restrict__ zeros_ri,
           float* __restrict__ out)
{
    __shared__ float  tile[2048];   // whole row, in-place x -> z
    __shared__ float2 ent[64];      // per-chunk true entry
    __shared__ float2 wex;          // warp-0 inclusive exit

    const int tid  = threadIdx.x;
    const int lane = tid & 31;
    const int w    = tid >> 5;
    const int row  = blockIdx.x;
    const float* xr = x   + (long)row * T_LEN;
    float*       yr = out + (long)row * T_LEN;

    // warp-edge boundary (x[1023], x[1022]) for warp 1 lane 0, via gmem
    float gx1 = 0.f, gx2 = 0.f;
    if (lane == 0 && w == 1) { gx1 = xr[1023]; gx2 = xr[1022]; }

    // ---- cp.async: warp w loads its own 4KB half, coalesced ----
    #pragma unroll
    for (int k = 0; k < 8; ++k) {
        int ch = w * 32 + k * 4 + (lane >> 3);
        cp_async16(tile + swz(ch, lane & 7), xr + w * 1024 + k * 128 + lane * 4);
    }
    cp_commit();

    // ---- coefficients + k-pair powers (overlap with loads) ----
    Coef c;
    {
        const float gr = gain_ri[0],  gi = gain_ri[1];
        const float pr0 = poles_ri[0], pi0 = poles_ri[1];
        const float pr1 = poles_ri[2], pi1 = poles_ri[3];
        const float zr0 = zeros_ri[0], zi0 = zeros_ri[1];
        const float zr1 = zeros_ri[2], zi1 = zeros_ri[3];
        c.a1 = -(pr0 + pr1);
        c.a2 = pr0 * pr1 - pi0 * pi1;
        const float zc1r = -(zr0 + zr1), zc1i = -(zi0 + zi1);
        const float zc2r = zr0 * zr1 - zi0 * zi1;
        const float zc2i = zr0 * zi1 + zi0 * zr1;
        c.b0 = gr;
        c.b1 = gr * zc1r - gi * zc1i;
        c.b2 = gr * zc2r - gi * zc2i;
        c.A2 = c.a1 * c.a1 - c.a2;
        c.Bc = c.a1 * c.a2;
    }
    const float a1 = c.a1, a2 = c.a2;
    K2 M1k  = { 1.f, 0.f };
    K2 M4k  = ksq(ksq(M1k, a1, a2), a1, a2);
    K2 M8k  = ksq(M4k, a1, a2);
    K2 M16k = ksq(M8k, a1, a2);
    K2 M32k = ksq(M16k, a1, a2);

    cp_wait0();
    __syncwarp();   // own warp's half resident & visible warp-wide

    // ---- boundary x[-1], x[-2] of this thread's 32-step chunk ----
    float x1, x2;
    if (lane > 0) {
        int cc = tid - 1;                       // same warp half
        int off = cc * 32 + ((7 ^ (cc & 7)) << 2);   // granule 7 = steps 28..31
        x1 = tile[off + 3];
        x2 = tile[off + 2];
    } else {
        x1 = gx1; x2 = gx2;                     // tid==0 -> zeros
    }
    __syncwarp();   // boundary reads done before Phase A overwrites tails

    // ---- Phase A: 32-step zero-entry recurrence in place ----
    float p = 0.f, q = 0.f;
    #pragma unroll
    for (int g = 0; g < 8; ++g) {
        float4 xv = *reinterpret_cast<float4*>(tile + swz(tid, g));
        float u0 = fmaf(c.b0, xv.x, fmaf(c.b1, x1,   c.b2 * x2));
        float u1 = fmaf(c.b0, xv.y, fmaf(c.b1, xv.x, c.b2 * x1));
        float u2 = fmaf(c.b0, xv.z, fmaf(c.b1, xv.y, c.b2 * xv.x));
        float u3 = fmaf(c.b0, xv.w, fmaf(c.b1, xv.z, c.b2 * xv.y));
        x2 = xv.z; x1 = xv.w;
        float w1 = fmaf(-a1, u0, u1);
        float w3 = fmaf(-a1, u2, u3);
        float yA = fmaf(-a1, p,  fmaf(-a2, q,  u0));
        float yB = fmaf( c.A2, p,  fmaf( c.Bc, q,  w1));
        float yC = fmaf(-a1, yB, fmaf(-a2, yA, u2));
        float yD = fmaf( c.A2, yB, fmaf( c.Bc, yA, w3));
        p = yD; q = yC;
        *reinterpret_cast<float4*>(tile + swz(tid, g)) = make_float4(yA, yB, yC, yD);
    }

    // ---- warp scan (T = M^32 k-form), A = M^(32*lane) built in-loop ----
    K2 m = M32k;
    K2 A = { 0.f, -1.f };   // identity
    float vx = p, vy = q;
    #pragma unroll
    for (int i = 0; i < 5; ++i) {
        float ox = __shfl_up_sync(0xffffffffu, vx, 1u << i);
        float oy = __shfl_up_sync(0xffffffffu, vy, 1u << i);
        if (lane >= (1 << i)) {
            float t = fmaf(-a1, ox, -a2 * oy);
            vx = fmaf(m.k1, t,  fmaf(-m.k2, ox, vx));
            vy = fmaf(m.k1, ox, fmaf(-m.k2, oy, vy));
        }
        if ((lane >> i) & 1) A = kmul(m, A, a1, a2);
        if (i < 4) m = ksq(m, a1, a2);
    }
    float ex = __shfl_up_sync(0xffffffffu, vx, 1);   // warp-local exclusive entry
    float ey = __shfl_up_sync(0xffffffffu, vy, 1);
    if (lane == 0) { ex = 0.f; ey = 0.f; }
    if (w == 0 && lane == 31) wex = make_float2(vx, vy);   // warp-0 exit

    __syncthreads();

    // ---- true entries: warp 0: E = e; warp 1: E = A*C + e, C = warp0 exit ----
    float Ex = ex, Ey = ey;
    if (w == 1) {
        float Cx = wex.x, Cy = wex.y;
        float t = fmaf(-a1, Cx, -a2 * Cy);
        Ex = fmaf(A.k1, t,  fmaf(-A.k2, Cx, ex));
        Ey = fmaf(A.k1, Cx, fmaf(-A.k2, Cy, ey));
    }
    ent[tid] = make_float2(Ex, Ey);

    __syncthreads();

    // ---- coalesced store with fused homogeneous correction ----
    // pos = it*256 + tid*4: chunk ch = it*8 + (tid>>3), granule j = tid&7,
    // seed = W*E(ch), W = M^(4j) as k-pair (per-lane constant).
    const int j = tid & 7;
    K2 W = { 0.f, -1.f };
    if (j & 1) W = M4k;
    if (j & 2) W = kmul(M8k,  W, a1, a2);
    if (j & 4) W = kmul(M16k, W, a1, a2);
    #pragma unroll
    for (int it = 0; it < 8; ++it) {
        int ch = it * 8 + (tid >> 3);
        float2 E = ent[ch];
        float t  = fmaf(-a1, E.x, -a2 * E.y);
        float s1 = fmaf(W.k1, t,   -W.k2 * E.x);
        float s2 = fmaf(W.k1, E.x, -W.k2 * E.y);
        float hA = fmaf(-a1, s1, -a2 * s2);
        float hB = fmaf( c.A2, s1,  c.Bc * s2);
        float hC = fmaf(-a1, hB, -a2 * hA);
        float hD = fmaf( c.A2, hB,  c.Bc * hA);
        float4 zv = *reinterpret_cast<float4*>(tile + swz(ch, j));
        zv.x += hA; zv.y += hB; zv.z += hC; zv.w += hD;
        *reinterpret_cast<float4*>(yr + it * 256 + tid * 4) = zv;
    }
}

extern "C" void kernel_launch(void* const* d_in, const int* in_sizes, int n_in,
                              void* d_out, int out_size) {
    (void)in_sizes; (void)n_in; (void)out_size;
    const float* x        = (const float*)d_in[0];
    const float* gain_ri  = (const float*)d_in[1];
    const float* poles_ri = (const float*)d_in[2];
    const float* zeros_ri = (const float*)d_in[3];
    float* out = (float*)d_out;

    pzE_kernel<<<B_ROWS, THREADS>>>(x, gain_ri, poles_ri, zeros_ri, out);
}